// round 14
// baseline (speedup 1.0000x reference)
#include <cuda_runtime.h>

// out = relu(cos(x+theta) @ W1 + b1) @ W2 + b2
// x: [B*S, 8] fp32, W1: [8,32], W2: [32,8], out: [B*S, 8] fp32
//
// R13: same compute structure as R12 (column-packed f32x2: weight pairs
// {w[2p],w[2p+1]} as multiplier, activation broadcast {a,a}; 4 rows/thread;
// accumulators in output order), but weights are read DIRECTLY from the
// input global pointers as packed u64 pairs — no __constant__ staging, no
// memcpy graph nodes (which cost ~6us of the 21.2us total last round).
// Weight addresses are warp-uniform -> single-wavefront broadcast LDGs,
// L1/L2 cached (all CTAs share the same 1.3KB).

using u64 = unsigned long long;

__device__ __forceinline__ u64 pack2(float lo, float hi) {
    u64 r;
    asm("mov.b64 %0, {%1, %2};" : "=l"(r) : "f"(lo), "f"(hi));
    return r;
}

__device__ __forceinline__ float2 unpack2(u64 v) {
    float2 f;
    asm("mov.b64 {%0, %1}, %2;" : "=f"(f.x), "=f"(f.y) : "l"(v));
    return f;
}

__device__ __forceinline__ u64 ffma2(u64 a, u64 b, u64 c) {
    u64 d;
    asm("fma.rn.f32x2 %0, %1, %2, %3;" : "=l"(d) : "l"(a), "l"(b), "l"(c));
    return d;
}

__device__ __forceinline__ u64 relu2(u64 v) {
    float2 f = unpack2(v);
    f.x = fmaxf(f.x, 0.0f);
    f.y = fmaxf(f.y, 0.0f);
    return pack2(f.x, f.y);
}

constexpr int E = 8;
constexpr int F = 32;
constexpr int R = 4;          // rows per thread
constexpr int BLOCK = 128;

__global__ __launch_bounds__(BLOCK)
void ffq_kernel(const float* __restrict__ x,
                const float* __restrict__ w1,   // [8][32] row-major
                const float* __restrict__ b1,   // [32]
                const float* __restrict__ w2,   // [32][8] row-major
                const float* __restrict__ b2,   // [8]
                const float* __restrict__ theta,// [8]
                float* __restrict__ out,
                long nrows)
{
    // Packed-pair views (raw little-endian reinterpretation of row-major f32):
    //   w1u[i*16 + jp] = {w1[i][2jp],  w1[i][2jp+1]}
    //   b1u[jp]        = {b1[2jp],     b1[2jp+1]}
    //   w2u[j*4 + ep]  = {w2[j][2ep],  w2[j][2ep+1]}
    //   b2u[ep]        = {b2[2ep],     b2[2ep+1]}
    const u64* __restrict__ w1u = (const u64*)w1;
    const u64* __restrict__ b1u = (const u64*)b1;
    const u64* __restrict__ w2u = (const u64*)w2;
    const u64* __restrict__ b2u = (const u64*)b2;

    const int t = threadIdx.x;
    const long row0 = ((long)blockIdx.x * BLOCK + t) * R;
    if (row0 >= nrows) return;

    float th[E];
#pragma unroll
    for (int i = 0; i < E; i++) th[i] = __ldg(&theta[i]);

    // ---- Load x: 8x LDG.128, fold into q = cos(x + theta) (scalar)
    const float4* xv = (const float4*)(x + row0 * E);
    float q[R][E];
#pragma unroll
    for (int r = 0; r < R; r++) {
        float4 a = xv[2 * r + 0];
        float4 b = xv[2 * r + 1];
        q[r][0] = __cosf(a.x + th[0]);
        q[r][1] = __cosf(a.y + th[1]);
        q[r][2] = __cosf(a.z + th[2]);
        q[r][3] = __cosf(a.w + th[3]);
        q[r][4] = __cosf(b.x + th[4]);
        q[r][5] = __cosf(b.y + th[5]);
        q[r][6] = __cosf(b.z + th[6]);
        q[r][7] = __cosf(b.w + th[7]);
    }

    // ---- Output accumulators: o2[r][ep] = {out[r][2ep], out[r][2ep+1]}
    u64 o2[R][E / 2];
#pragma unroll
    for (int ep = 0; ep < E / 2; ep++) {
        u64 b = __ldg(&b2u[ep]);
#pragma unroll
        for (int r = 0; r < R; r++) o2[r][ep] = b;
    }

    // ---- Hidden dim in groups of 8 columns (4 column-pairs)
#pragma unroll
    for (int jg = 0; jg < F / 8; jg++) {
        const int jp0 = jg * 4;          // first column-pair of this group
        const int j0  = jg * 8;          // first column of this group

        // layer 1: h[r][p] = {h[r][j0+2p], h[r][j0+2p+1]}
        u64 h[R][4];
#pragma unroll
        for (int p = 0; p < 4; p++) {
            u64 b = __ldg(&b1u[jp0 + p]);
#pragma unroll
            for (int r = 0; r < R; r++) h[r][p] = b;
        }
#pragma unroll
        for (int i = 0; i < E; i++) {
            // 4 uniform-broadcast weight LDGs feed 16 FFMA2s
            u64 w0 = __ldg(&w1u[i * 16 + jp0 + 0]);
            u64 w1v = __ldg(&w1u[i * 16 + jp0 + 1]);
            u64 w2v = __ldg(&w1u[i * 16 + jp0 + 2]);
            u64 w3 = __ldg(&w1u[i * 16 + jp0 + 3]);
#pragma unroll
            for (int r = 0; r < R; r++) {
                u64 qb = pack2(q[r][i], q[r][i]);   // 1 MOV, feeds 4 FFMA2
                h[r][0] = ffma2(qb, w0,  h[r][0]);
                h[r][1] = ffma2(qb, w1v, h[r][1]);
                h[r][2] = ffma2(qb, w2v, h[r][2]);
                h[r][3] = ffma2(qb, w3,  h[r][3]);
            }
        }

        // relu
#pragma unroll
        for (int r = 0; r < R; r++) {
#pragma unroll
            for (int p = 0; p < 4; p++) h[r][p] = relu2(h[r][p]);
        }

        // layer 2: for each column j in group, broadcast h and accumulate
#pragma unroll
        for (int jj = 0; jj < 8; jj++) {
            const int j = j0 + jj;
            u64 v0 = __ldg(&w2u[j * 4 + 0]);
            u64 v1 = __ldg(&w2u[j * 4 + 1]);
            u64 v2 = __ldg(&w2u[j * 4 + 2]);
            u64 v3 = __ldg(&w2u[j * 4 + 3]);
#pragma unroll
            for (int r = 0; r < R; r++) {
                float2 hf = unpack2(h[r][jj >> 1]);   // free (reg aliasing)
                float hv = (jj & 1) ? hf.y : hf.x;
                u64 hb = pack2(hv, hv);               // 1 MOV, feeds 4 FFMA2
                o2[r][0] = ffma2(hb, v0, o2[r][0]);
                o2[r][1] = ffma2(hb, v1, o2[r][1]);
                o2[r][2] = ffma2(hb, v2, o2[r][2]);
                o2[r][3] = ffma2(hb, v3, o2[r][3]);
            }
        }
    }

    // ---- Store: o2[r] is row r's 8 outputs in order -> 2x STG.128 per row
    float4* ov = (float4*)(out + row0 * E);
#pragma unroll
    for (int r = 0; r < R; r++) {
        float2 f0 = unpack2(o2[r][0]);
        float2 f1 = unpack2(o2[r][1]);
        float2 f2 = unpack2(o2[r][2]);
        float2 f3 = unpack2(o2[r][3]);
        ov[2 * r + 0] = make_float4(f0.x, f0.y, f1.x, f1.y);
        ov[2 * r + 1] = make_float4(f2.x, f2.y, f3.x, f3.y);
    }
}

extern "C" void kernel_launch(void* const* d_in, const int* in_sizes, int n_in,
                              void* d_out, int out_size)
{
    const float* x     = (const float*)d_in[0];
    const float* theta = (const float*)d_in[1];
    const float* w1    = (const float*)d_in[2];
    const float* b1    = (const float*)d_in[3];
    const float* w2    = (const float*)d_in[4];
    const float* b2    = (const float*)d_in[5];
    float* out = (float*)d_out;

    const long nrows = (long)in_sizes[0] / E;  // 524288
    const long nthreads = (nrows + R - 1) / R;
    const int grid = (int)((nthreads + BLOCK - 1) / BLOCK);

    ffq_kernel<<<grid, BLOCK>>>(x, w1, b1, w2, b2, theta, out, nrows);
}